// round 5
// baseline (speedup 1.0000x reference)
#include <cuda_runtime.h>
#include <cstdint>

// ---------------------------------------------------------------------------
// Problem constants
// ---------------------------------------------------------------------------
#define B_ROWS   16384
#define LCOLS    512
#define LP       514                     // L + 2

// Scratch: 1 byte per (channel, row, col<512):
//   bits [1:0] sub data, [2] sub mask, [3] del keep, [4] ins flag, [6:5] ins sym
__device__ uint8_t g_scratch[4u * B_ROWS * LCOLS];   // 32 MiB

struct AllKeys {
    // [channel][stream][2]; stream: 0=data 1=mask 2=keep 3=ins 4=sym
    uint32_t k[4][5][2];
};

// ---------------------------------------------------------------------------
// threefry2x32 (exact JAX schedule)
// ---------------------------------------------------------------------------
__host__ __device__ __forceinline__ uint32_t rotl32(uint32_t v, int r) {
#ifdef __CUDA_ARCH__
    return __funnelshift_l(v, v, r);
#else
    return (v << r) | (v >> (32 - r));
#endif
}

#define TF_ROUND(x0, x1, r) do { (x0) += (x1); (x1) = rotl32((x1), (r)); (x1) ^= (x0); } while (0)
#define TF_R4A(x0, x1) do { TF_ROUND(x0,x1,13); TF_ROUND(x0,x1,15); TF_ROUND(x0,x1,26); TF_ROUND(x0,x1,6);  } while (0)
#define TF_R4B(x0, x1) do { TF_ROUND(x0,x1,17); TF_ROUND(x0,x1,29); TF_ROUND(x0,x1,16); TF_ROUND(x0,x1,24); } while (0)

__host__ __device__ __forceinline__ void tf2(uint32_t k0, uint32_t k1,
                                             uint32_t& x0, uint32_t& x1) {
    uint32_t k2 = k0 ^ k1 ^ 0x1BD11BDAu;
    x0 += k0; x1 += k1;
    TF_R4A(x0, x1); x0 += k1; x1 += k2 + 1u;
    TF_R4B(x0, x1); x0 += k2; x1 += k0 + 2u;
    TF_R4A(x0, x1); x0 += k0; x1 += k1 + 3u;
    TF_R4B(x0, x1); x0 += k1; x1 += k2 + 4u;
    TF_R4A(x0, x1); x0 += k2; x1 += k0 + 5u;
}

// Partitionable random_bits, 32-bit width: element with 64-bit counter (0, c)
// yields bits = o0 ^ o1 of the threefry block.  (Confirmed exact by data.)
__device__ __forceinline__ uint32_t pbits(uint32_t k0, uint32_t k1, uint32_t c) {
    uint32_t x0 = 0u, x1 = c;
    tf2(k0, k1, x0, x1);
    return x0 ^ x1;
}

__device__ __forceinline__ float bits_to_uniform(uint32_t b) {
    // jax: bitcast((bits >> 9) | 0x3f800000) - 1.0   in [0,1)
    return __uint_as_float((b >> 9) | 0x3f800000u) - 1.0f;
}

// ---------------------------------------------------------------------------
// Kernel 1: generate all random decisions, packed 1B/(ch,row,col).
// One thread per element; 5 independent threefry blocks (good ILP).
// randint(0,4): _randint splits its key -> (k1,k2); multiplier==0 for span=4,
// so value = random_bits(k2,32,shape) & 3.  K.k[..][0]/[4] hold that k2.
// ---------------------------------------------------------------------------
__global__ void __launch_bounds__(256) gen_kernel(AllKeys K,
                                                  const float* __restrict__ p_sub,
                                                  const float* __restrict__ p_del,
                                                  const float* __restrict__ p_ins) {
    uint32_t tid = blockIdx.x * blockDim.x + threadIdx.x;   // 2^25 threads exactly
    uint32_t l  = tid & (LCOLS - 1);
    uint32_t b  = (tid >> 9) & (B_ROWS - 1);
    uint32_t ch = tid >> 23;

    const float sub_e = *p_sub;
    const float del_e = *p_del;
    const float ins_e = *p_ins;

    const uint32_t i1 = b * LCOLS + l;   // index in (B,512) streams
    const uint32_t i2 = b * LP + l;      // index in (B,514) streams

    uint32_t dat  = pbits(K.k[ch][0][0], K.k[ch][0][1], i1) & 3u;
    uint32_t mskb = bits_to_uniform(pbits(K.k[ch][1][0], K.k[ch][1][1], i1)) < sub_e;
    uint32_t keep = bits_to_uniform(pbits(K.k[ch][2][0], K.k[ch][2][1], i1)) >= del_e;
    uint32_t insf = bits_to_uniform(pbits(K.k[ch][3][0], K.k[ch][3][1], i2)) < ins_e;
    uint32_t sym  = pbits(K.k[ch][4][0], K.k[ch][4][1], i2) & 3u;

    uint8_t byte = (uint8_t)(dat | (mskb << 2) | (keep << 3) | (insf << 4) | (sym << 5));
    g_scratch[((size_t)ch * B_ROWS + b) * LCOLS + l] = byte;   // coalesced in l
}

// ---------------------------------------------------------------------------
// Kernel 2: per-row channel simulation. One warp per (row, channel).
// Sequential semantics: for each original col (in order): if kept, emit its
// (substituted) value; if the survivor's ins flag is set, emit the sym after.
// Truncate at 514, pad with 0 (== -1 + 1).
// ---------------------------------------------------------------------------
__global__ void __launch_bounds__(256) scan_kernel(const float* __restrict__ x,
                                                   float* __restrict__ out) {
    uint32_t gwid = (blockIdx.x * blockDim.x + threadIdx.x) >> 5;  // 65536 warps
    uint32_t lane = threadIdx.x & 31;
    uint32_t ch = gwid & 3u;
    uint32_t b  = gwid >> 2;

    const uint8_t* srow = g_scratch + (((size_t)ch * B_ROWS) + b) * LCOLS;
    const float*   xrow = x + (size_t)b * LCOLS;
    float*         orow = out + ((size_t)b * 4u + ch) * LP;

    const uint32_t lt = (1u << lane) - 1u;
    uint32_t srank = 0;   // survivors emitted so far
    uint32_t itot  = 0;   // insertions emitted so far

    #pragma unroll 1
    for (int w = 0; w < LCOLS / 32; ++w) {
        uint32_t c = srank + itot;          // warp-uniform emit cursor
        if (c >= LP) break;                 // everything further would be clipped

        int l = w * 32 + (int)lane;
        uint8_t byte = srow[l];
        int xi   = (int)xrow[l];
        int dat  = byte & 3;
        int mskb = (byte >> 2) & 1;
        int keep = (byte >> 3) & 1;
        int val  = (xi + dat * mskb) & 3;

        unsigned kmask = __ballot_sync(0xffffffffu, keep);
        int rank_local = __popc(kmask & lt);

        int insf = 0, sym = 0;
        if (keep) {
            // survivor index (rank in post-deletion array) selects ins/sym
            uint8_t ib = srow[srank + (uint32_t)rank_local];   // rank < 512 always
            insf = (ib >> 4) & 1;
            sym  = (ib >> 5) & 3;
        }
        unsigned imask = __ballot_sync(0xffffffffu, keep && insf);

        if (keep) {
            uint32_t pos = c + (uint32_t)rank_local + (uint32_t)__popc(imask & lt);
            if (pos < LP)               orow[pos]     = (float)(val + 1);
            if (insf && pos + 1 < LP)   orow[pos + 1] = (float)(sym + 1);
        }
        srank += __popc(kmask);
        itot  += __popc(imask);
    }

    // tail = -1 padding, +1.0 => 0.0
    uint32_t cend = srank + itot;
    if (cend > LP) cend = LP;
    for (uint32_t j = cend + lane; j < LP; j += 32) orow[j] = 0.0f;
}

// ---------------------------------------------------------------------------
// Host: derive the full JAX key tree (partitionable / fold-like semantics:
// every derived key = threefry(parent, (0, index)) yielding the (o0, o1) pair)
// ---------------------------------------------------------------------------
static inline void h_key(uint32_t k0, uint32_t k1, uint32_t idx,
                         uint32_t& o0, uint32_t& o1) {
    uint32_t x0 = 0u, x1 = idx;
    tf2(k0, k1, x0, x1);
    o0 = x0; o1 = x1;
}

extern "C" void kernel_launch(void* const* d_in, const int* in_sizes, int n_in,
                              void* d_out, int out_size) {
    const float* x     = (const float*)d_in[0];
    const float* p_sub = (const float*)d_in[1];
    const float* p_del = (const float*)d_in[2];
    const float* p_ins = (const float*)d_in[3];

    AllKeys K;
    const uint32_t base0 = 0u, base1 = 42u;           // jax.random.key(42) -> (0, 42)
    for (uint32_t c = 0; c < 4; ++c) {
        uint32_t kc0, kc1;
        h_key(base0, base1, c, kc0, kc1);             // fold_in(key, c)

        // split(kc, 3) fold-like: key_i = tf(kc, (0, i))
        uint32_t k1_0, k1_1, k2_0, k2_1, k3_0, k3_1;
        h_key(kc0, kc1, 0u, k1_0, k1_1);              // sub key
        h_key(kc0, kc1, 1u, k2_0, k2_1);              // del key
        h_key(kc0, kc1, 2u, k3_0, k3_1);              // ins key

        // sub: split(k1, 2) -> data key (randint), mask key (uniform)
        uint32_t kd0, kd1;
        h_key(k1_0, k1_1, 0u, kd0, kd1);              // randint outer key
        // _randint internal split: lower_bits uses child 1
        h_key(kd0, kd1, 1u, K.k[c][0][0], K.k[c][0][1]);     // data low-bits key
        h_key(k1_0, k1_1, 1u, K.k[c][1][0], K.k[c][1][1]);   // mask (uniform)

        // del: uses k2 directly
        K.k[c][2][0] = k2_0; K.k[c][2][1] = k2_1;

        // ins: split(k3, 2) -> flag key (uniform), sym key (randint)
        h_key(k3_0, k3_1, 0u, K.k[c][3][0], K.k[c][3][1]);   // ins flag (uniform)
        uint32_t ks0, ks1;
        h_key(k3_0, k3_1, 1u, ks0, ks1);              // randint outer key
        h_key(ks0, ks1, 1u, K.k[c][4][0], K.k[c][4][1]);     // sym low-bits key
    }

    // Kernel 1: 4 * 16384 * 512 = 2^25 threads
    gen_kernel<<<131072, 256>>>(K, p_sub, p_del, p_ins);
    // Kernel 2: 65536 warps = 2^21 threads
    scan_kernel<<<8192, 256>>>(x, (float*)d_out);
}

// round 6
// speedup vs baseline: 1.2090x; 1.2090x over previous
#include <cuda_runtime.h>
#include <cstdint>

// ---------------------------------------------------------------------------
// Problem constants
// ---------------------------------------------------------------------------
#define B_ROWS   16384
#define LCOLS    512
#define LP       514                     // L + 2

// Scratch: 1 byte per (channel, row, col<512):
//   bits [1:0] sub data, [2] sub mask, [3] del keep, [4] ins flag, [6:5] ins sym
__device__ uint8_t g_scratch[4u * B_ROWS * LCOLS];   // 32 MiB

struct AllKeys {
    // [channel][stream][2]; stream: 0=data 1=mask 2=keep 3=ins 4=sym
    uint32_t k[4][5][2];
};

// ---------------------------------------------------------------------------
// threefry2x32 (exact JAX schedule)
// ---------------------------------------------------------------------------
__host__ __device__ __forceinline__ uint32_t rotl32(uint32_t v, int r) {
#ifdef __CUDA_ARCH__
    return __funnelshift_l(v, v, r);
#else
    return (v << r) | (v >> (32 - r));
#endif
}

#define TF_ROUND(x0, x1, r) do { (x0) += (x1); (x1) = rotl32((x1), (r)); (x1) ^= (x0); } while (0)
#define TF_R4A(x0, x1) do { TF_ROUND(x0,x1,13); TF_ROUND(x0,x1,15); TF_ROUND(x0,x1,26); TF_ROUND(x0,x1,6);  } while (0)
#define TF_R4B(x0, x1) do { TF_ROUND(x0,x1,17); TF_ROUND(x0,x1,29); TF_ROUND(x0,x1,16); TF_ROUND(x0,x1,24); } while (0)

__host__ __device__ __forceinline__ void tf2(uint32_t k0, uint32_t k1,
                                             uint32_t& x0, uint32_t& x1) {
    uint32_t k2 = k0 ^ k1 ^ 0x1BD11BDAu;
    x0 += k0; x1 += k1;
    TF_R4A(x0, x1); x0 += k1; x1 += k2 + 1u;
    TF_R4B(x0, x1); x0 += k2; x1 += k0 + 2u;
    TF_R4A(x0, x1); x0 += k0; x1 += k1 + 3u;
    TF_R4B(x0, x1); x0 += k1; x1 += k2 + 4u;
    TF_R4A(x0, x1); x0 += k2; x1 += k0 + 5u;
}

// Partitionable random_bits, 32-bit width: element with 64-bit counter (0, c)
// yields bits = o0 ^ o1 of the threefry block.  (Confirmed exact by data.)
__device__ __forceinline__ uint32_t pbits(uint32_t k0, uint32_t k1, uint32_t c) {
    uint32_t x0 = 0u, x1 = c;
    tf2(k0, k1, x0, x1);
    return x0 ^ x1;
}

// ---------------------------------------------------------------------------
// Kernel 1: generate all random decisions, packed 1B/(ch,row,col).
// uniform(bits) < e  ⟺  (bits>>9) < ceil(e * 2^23)   (exact; see notes)
// dat/sym threefry blocks are ballot-skipped when no lane in the warp needs
// them (p_skip = 0.98^32 = 0.52 and 0.99^32 = 0.725 respectively).
// ---------------------------------------------------------------------------
__global__ void __launch_bounds__(256) gen_kernel(AllKeys K,
                                                  const float* __restrict__ p_sub,
                                                  const float* __restrict__ p_del,
                                                  const float* __restrict__ p_ins) {
    uint32_t tid = blockIdx.x * blockDim.x + threadIdx.x;   // 2^25 threads exactly
    uint32_t l  = tid & (LCOLS - 1);
    uint32_t b  = (tid >> 9) & (B_ROWS - 1);
    uint32_t ch = tid >> 23;

    const uint32_t thr_sub = (uint32_t)ceilf(*p_sub * 8388608.0f);
    const uint32_t thr_del = (uint32_t)ceilf(*p_del * 8388608.0f);
    const uint32_t thr_ins = (uint32_t)ceilf(*p_ins * 8388608.0f);

    const uint32_t i1 = b * LCOLS + l;   // index in (B,512) streams
    const uint32_t i2 = b * LP + l;      // index in (B,514) streams

    uint32_t mskb = (pbits(K.k[ch][1][0], K.k[ch][1][1], i1) >> 9) < thr_sub;
    uint32_t keep = (pbits(K.k[ch][2][0], K.k[ch][2][1], i1) >> 9) >= thr_del;
    uint32_t insf = (pbits(K.k[ch][3][0], K.k[ch][3][1], i2) >> 9) < thr_ins;

    uint32_t dat = 0, sym = 0;
    if (__ballot_sync(0xffffffffu, mskb))
        dat = pbits(K.k[ch][0][0], K.k[ch][0][1], i1) & 3u;
    if (__ballot_sync(0xffffffffu, insf))
        sym = pbits(K.k[ch][4][0], K.k[ch][4][1], i2) & 3u;

    uint8_t byte = (uint8_t)(dat | (mskb << 2) | (keep << 3) | (insf << 4) | (sym << 5));
    g_scratch[((size_t)ch * B_ROWS + b) * LCOLS + l] = byte;   // coalesced in l
}

// ---------------------------------------------------------------------------
// Kernel 2: per-row channel simulation. One warp per (row, channel).
// Sequential semantics: for each original col (in order): if kept, emit its
// (substituted) value; if the survivor's ins flag is set, emit the sym after.
// Truncate at 514, pad with 0 (== -1 + 1).
// ---------------------------------------------------------------------------
__global__ void __launch_bounds__(256) scan_kernel(const float* __restrict__ x,
                                                   float* __restrict__ out) {
    uint32_t gwid = (blockIdx.x * blockDim.x + threadIdx.x) >> 5;  // 65536 warps
    uint32_t lane = threadIdx.x & 31;
    uint32_t ch = gwid & 3u;
    uint32_t b  = gwid >> 2;

    const uint8_t* srow = g_scratch + (((size_t)ch * B_ROWS) + b) * LCOLS;
    const float*   xrow = x + (size_t)b * LCOLS;
    float*         orow = out + ((size_t)b * 4u + ch) * LP;

    const uint32_t lt = (1u << lane) - 1u;
    uint32_t srank = 0;   // survivors emitted so far
    uint32_t itot  = 0;   // insertions emitted so far

    #pragma unroll 1
    for (int w = 0; w < LCOLS / 32; ++w) {
        uint32_t c = srank + itot;          // warp-uniform emit cursor
        if (c >= LP) break;                 // everything further would be clipped

        int l = w * 32 + (int)lane;
        uint8_t byte = srow[l];
        int xi   = (int)xrow[l];
        int dat  = byte & 3;
        int mskb = (byte >> 2) & 1;
        int keep = (byte >> 3) & 1;
        int val  = (xi + dat * mskb) & 3;

        unsigned kmask = __ballot_sync(0xffffffffu, keep);
        int rank_local = __popc(kmask & lt);

        int insf = 0, sym = 0;
        if (keep) {
            // survivor index (rank in post-deletion array) selects ins/sym
            uint8_t ib = srow[srank + (uint32_t)rank_local];   // rank < 512 always
            insf = (ib >> 4) & 1;
            sym  = (ib >> 5) & 3;
        }
        unsigned imask = __ballot_sync(0xffffffffu, keep && insf);

        if (keep) {
            uint32_t pos = c + (uint32_t)rank_local + (uint32_t)__popc(imask & lt);
            if (pos < LP)               orow[pos]     = (float)(val + 1);
            if (insf && pos + 1 < LP)   orow[pos + 1] = (float)(sym + 1);
        }
        srank += __popc(kmask);
        itot  += __popc(imask);
    }

    // tail = -1 padding, +1.0 => 0.0
    uint32_t cend = srank + itot;
    if (cend > LP) cend = LP;
    for (uint32_t j = cend + lane; j < LP; j += 32) orow[j] = 0.0f;
}

// ---------------------------------------------------------------------------
// Host: derive the full JAX key tree (partitionable / fold-like semantics:
// every derived key = threefry(parent, (0, index)) yielding the (o0, o1) pair)
// ---------------------------------------------------------------------------
static inline void h_key(uint32_t k0, uint32_t k1, uint32_t idx,
                         uint32_t& o0, uint32_t& o1) {
    uint32_t x0 = 0u, x1 = idx;
    tf2(k0, k1, x0, x1);
    o0 = x0; o1 = x1;
}

extern "C" void kernel_launch(void* const* d_in, const int* in_sizes, int n_in,
                              void* d_out, int out_size) {
    const float* x     = (const float*)d_in[0];
    const float* p_sub = (const float*)d_in[1];
    const float* p_del = (const float*)d_in[2];
    const float* p_ins = (const float*)d_in[3];

    AllKeys K;
    const uint32_t base0 = 0u, base1 = 42u;           // jax.random.key(42) -> (0, 42)
    for (uint32_t c = 0; c < 4; ++c) {
        uint32_t kc0, kc1;
        h_key(base0, base1, c, kc0, kc1);             // fold_in(key, c)

        // split(kc, 3) fold-like: key_i = tf(kc, (0, i))
        uint32_t k1_0, k1_1, k2_0, k2_1, k3_0, k3_1;
        h_key(kc0, kc1, 0u, k1_0, k1_1);              // sub key
        h_key(kc0, kc1, 1u, k2_0, k2_1);              // del key
        h_key(kc0, kc1, 2u, k3_0, k3_1);              // ins key

        // sub: split(k1, 2) -> data key (randint), mask key (uniform)
        uint32_t kd0, kd1;
        h_key(k1_0, k1_1, 0u, kd0, kd1);              // randint outer key
        // _randint internal split: lower_bits uses child 1
        h_key(kd0, kd1, 1u, K.k[c][0][0], K.k[c][0][1]);     // data low-bits key
        h_key(k1_0, k1_1, 1u, K.k[c][1][0], K.k[c][1][1]);   // mask (uniform)

        // del: uses k2 directly
        K.k[c][2][0] = k2_0; K.k[c][2][1] = k2_1;

        // ins: split(k3, 2) -> flag key (uniform), sym key (randint)
        h_key(k3_0, k3_1, 0u, K.k[c][3][0], K.k[c][3][1]);   // ins flag (uniform)
        uint32_t ks0, ks1;
        h_key(k3_0, k3_1, 1u, ks0, ks1);              // randint outer key
        h_key(ks0, ks1, 1u, K.k[c][4][0], K.k[c][4][1]);     // sym low-bits key
    }

    // Kernel 1: 4 * 16384 * 512 = 2^25 threads
    gen_kernel<<<131072, 256>>>(K, p_sub, p_del, p_ins);
    // Kernel 2: 65536 warps = 2^21 threads
    scan_kernel<<<8192, 256>>>(x, (float*)d_out);
}

// round 7
// speedup vs baseline: 1.4116x; 1.1676x over previous
#include <cuda_runtime.h>
#include <cstdint>

// ---------------------------------------------------------------------------
// Problem constants
// ---------------------------------------------------------------------------
#define B_ROWS   16384
#define LCOLS    512
#define LP       514                     // L + 2

struct AllKeys {
    // [channel][stream][2]; stream: 0=data 1=mask 2=keep 3=ins 4=sym
    uint32_t k[4][5][2];
};

// ---------------------------------------------------------------------------
// threefry2x32 (exact JAX schedule)
// ---------------------------------------------------------------------------
__host__ __device__ __forceinline__ uint32_t rotl32(uint32_t v, int r) {
#ifdef __CUDA_ARCH__
    return __funnelshift_l(v, v, r);
#else
    return (v << r) | (v >> (32 - r));
#endif
}

#define TF_ROUND(x0, x1, r) do { (x0) += (x1); (x1) = rotl32((x1), (r)); (x1) ^= (x0); } while (0)
#define TF_R4A(x0, x1) do { TF_ROUND(x0,x1,13); TF_ROUND(x0,x1,15); TF_ROUND(x0,x1,26); TF_ROUND(x0,x1,6);  } while (0)
#define TF_R4B(x0, x1) do { TF_ROUND(x0,x1,17); TF_ROUND(x0,x1,29); TF_ROUND(x0,x1,16); TF_ROUND(x0,x1,24); } while (0)

__host__ __device__ __forceinline__ void tf2(uint32_t k0, uint32_t k1,
                                             uint32_t& x0, uint32_t& x1) {
    uint32_t k2 = k0 ^ k1 ^ 0x1BD11BDAu;
    x0 += k0; x1 += k1;
    TF_R4A(x0, x1); x0 += k1; x1 += k2 + 1u;
    TF_R4B(x0, x1); x0 += k2; x1 += k0 + 2u;
    TF_R4A(x0, x1); x0 += k0; x1 += k1 + 3u;
    TF_R4B(x0, x1); x0 += k1; x1 += k2 + 4u;
    TF_R4A(x0, x1); x0 += k2; x1 += k0 + 5u;
}

// Partitionable random_bits, 32-bit width: bits = o0 ^ o1 at counter (0, c).
__device__ __forceinline__ uint32_t pbits(uint32_t k0, uint32_t k1, uint32_t c) {
    uint32_t x0 = 0u, x1 = c;
    tf2(k0, k1, x0, x1);
    return x0 ^ x1;
}

// ---------------------------------------------------------------------------
// Fused kernel: one warp per (row, channel). For each 32-elem chunk:
//   gen phase: threefry streams (uniforms as integer threshold compares,
//              exact: u < e  <=>  (bits>>9) < ceil(e*2^23); rare dat/sym
//              blocks ballot-skipped), stash insf|sym<<1 in smem row buffer.
//   scan phase: warp stream-compaction + insertion emit, sequential-exact.
// No global scratch; output written directly.
// ---------------------------------------------------------------------------
__global__ void __launch_bounds__(256) fused_kernel(AllKeys K,
                                                    const float* __restrict__ x,
                                                    const float* __restrict__ p_sub,
                                                    const float* __restrict__ p_del,
                                                    const float* __restrict__ p_ins,
                                                    float* __restrict__ out) {
    __shared__ uint8_t rowbuf[8][LCOLS];

    const uint32_t wib  = threadIdx.x >> 5;
    const uint32_t lane = threadIdx.x & 31u;
    const uint32_t gw   = blockIdx.x * 8u + wib;       // 65536 warps
    const uint32_t ch   = gw & 3u;
    const uint32_t b    = gw >> 2;

    const uint32_t thr_sub = (uint32_t)ceilf(*p_sub * 8388608.0f);
    const uint32_t thr_del = (uint32_t)ceilf(*p_del * 8388608.0f);
    const uint32_t thr_ins = (uint32_t)ceilf(*p_ins * 8388608.0f);

    const uint32_t kd0 = K.k[ch][0][0], kd1 = K.k[ch][0][1];
    const uint32_t km0 = K.k[ch][1][0], km1 = K.k[ch][1][1];
    const uint32_t kk0 = K.k[ch][2][0], kk1 = K.k[ch][2][1];
    const uint32_t ki0 = K.k[ch][3][0], ki1 = K.k[ch][3][1];
    const uint32_t ks0 = K.k[ch][4][0], ks1 = K.k[ch][4][1];

    const float* xrow = x + (size_t)b * LCOLS;
    float*       orow = out + ((size_t)b * 4u + ch) * LP;
    uint8_t*     srow = rowbuf[wib];

    const uint32_t lt = (1u << lane) - 1u;
    uint32_t srank = 0;   // survivors emitted so far
    uint32_t itot  = 0;   // insertions emitted so far

    #pragma unroll 1
    for (int w = 0; w < LCOLS / 32; ++w) {
        const uint32_t l  = (uint32_t)w * 32u + lane;
        const uint32_t i1 = b * LCOLS + l;   // (B,512) stream index
        const uint32_t i2 = b * LP + l;      // (B,514) stream index

        // ---- gen phase ----
        uint32_t mskb = (pbits(km0, km1, i1) >> 9) < thr_sub;
        uint32_t keep = (pbits(kk0, kk1, i1) >> 9) >= thr_del;
        uint32_t insf = (pbits(ki0, ki1, i2) >> 9) < thr_ins;

        uint32_t dat = 0, sym = 0;
        if (__ballot_sync(0xffffffffu, mskb))
            dat = pbits(kd0, kd1, i1) & 3u;
        if (__ballot_sync(0xffffffffu, insf))
            sym = pbits(ks0, ks1, i2) & 3u;

        srow[l] = (uint8_t)(insf | (sym << 1));
        __syncwarp();

        // ---- scan phase ----
        int xi  = (int)xrow[l];
        int val = (int)(((uint32_t)xi + dat * mskb) & 3u);

        unsigned kmask = __ballot_sync(0xffffffffu, keep);
        int rank_local = __popc(kmask & lt);

        int insf2 = 0, sym2 = 0;
        if (keep) {
            // survivor rank indexes ins/sym (rank <= current position, so the
            // byte was written this chunk or earlier)
            uint8_t ib = srow[srank + (uint32_t)rank_local];
            insf2 = ib & 1;
            sym2  = (ib >> 1) & 3;
        }
        unsigned imask = __ballot_sync(0xffffffffu, keep && insf2);

        if (keep) {
            uint32_t pos = srank + itot + (uint32_t)rank_local
                         + (uint32_t)__popc(imask & lt);
            if (pos < LP)                orow[pos]     = (float)(val + 1);
            if (insf2 && pos + 1 < LP)   orow[pos + 1] = (float)(sym2 + 1);
        }
        srank += __popc(kmask);
        itot  += __popc(imask);
    }

    // tail = -1 padding, +1.0 => 0.0
    uint32_t cend = srank + itot;
    if (cend > LP) cend = LP;
    for (uint32_t j = cend + lane; j < LP; j += 32) orow[j] = 0.0f;
}

// ---------------------------------------------------------------------------
// Host: derive the full JAX key tree (partitionable / fold-like semantics:
// every derived key = threefry(parent, (0, index)) yielding the (o0, o1) pair)
// ---------------------------------------------------------------------------
static inline void h_key(uint32_t k0, uint32_t k1, uint32_t idx,
                         uint32_t& o0, uint32_t& o1) {
    uint32_t x0 = 0u, x1 = idx;
    tf2(k0, k1, x0, x1);
    o0 = x0; o1 = x1;
}

extern "C" void kernel_launch(void* const* d_in, const int* in_sizes, int n_in,
                              void* d_out, int out_size) {
    const float* x     = (const float*)d_in[0];
    const float* p_sub = (const float*)d_in[1];
    const float* p_del = (const float*)d_in[2];
    const float* p_ins = (const float*)d_in[3];

    AllKeys K;
    const uint32_t base0 = 0u, base1 = 42u;           // jax.random.key(42) -> (0, 42)
    for (uint32_t c = 0; c < 4; ++c) {
        uint32_t kc0, kc1;
        h_key(base0, base1, c, kc0, kc1);             // fold_in(key, c)

        // split(kc, 3) fold-like: key_i = tf(kc, (0, i))
        uint32_t k1_0, k1_1, k2_0, k2_1, k3_0, k3_1;
        h_key(kc0, kc1, 0u, k1_0, k1_1);              // sub key
        h_key(kc0, kc1, 1u, k2_0, k2_1);              // del key
        h_key(kc0, kc1, 2u, k3_0, k3_1);              // ins key

        // sub: split(k1, 2) -> data key (randint), mask key (uniform)
        uint32_t kd0, kd1;
        h_key(k1_0, k1_1, 0u, kd0, kd1);              // randint outer key
        // _randint internal split: lower_bits uses child 1
        h_key(kd0, kd1, 1u, K.k[c][0][0], K.k[c][0][1]);     // data low-bits key
        h_key(k1_0, k1_1, 1u, K.k[c][1][0], K.k[c][1][1]);   // mask (uniform)

        // del: uses k2 directly
        K.k[c][2][0] = k2_0; K.k[c][2][1] = k2_1;

        // ins: split(k3, 2) -> flag key (uniform), sym key (randint)
        h_key(k3_0, k3_1, 0u, K.k[c][3][0], K.k[c][3][1]);   // ins flag (uniform)
        uint32_t ks0, ks1;
        h_key(k3_0, k3_1, 1u, ks0, ks1);              // randint outer key
        h_key(ks0, ks1, 1u, K.k[c][4][0], K.k[c][4][1]);     // sym low-bits key
    }

    // 65536 warps (one per row x channel) = 8192 blocks x 256 threads
    fused_kernel<<<8192, 256>>>(K, x, p_sub, p_del, p_ins, (float*)d_out);
}

// round 8
// speedup vs baseline: 1.6394x; 1.1614x over previous
#include <cuda_runtime.h>
#include <cstdint>

// ---------------------------------------------------------------------------
// Problem constants
// ---------------------------------------------------------------------------
#define B_ROWS   16384
#define LCOLS    512
#define LP       514                     // L + 2

// Per-stream threefry constants with key-schedule adds prefolded (host-side).
struct StreamK {
    uint32_t i0, i1;                     // x0 = i0, x1 = c + i1
    uint32_t a1, b1, a2, b2, a3, b3, a4, b4, a5, b5;   // injection adds
};
struct GenParams {
    StreamK s[4][5];   // [channel][stream]; 0=data 1=mask 2=keep 3=ins 4=sym
};

// ---------------------------------------------------------------------------
// threefry2x32 (exact JAX schedule)
// ---------------------------------------------------------------------------
__host__ __device__ __forceinline__ uint32_t rotl32(uint32_t v, int r) {
#ifdef __CUDA_ARCH__
    return __funnelshift_l(v, v, r);
#else
    return (v << r) | (v >> (32 - r));
#endif
}

// Host-side reference tf2 (key-tree derivation only)
#define TF_ROUND_H(x0, x1, r) do { (x0) += (x1); (x1) = rotl32((x1), (r)); (x1) ^= (x0); } while (0)
static inline void h_tf2(uint32_t k0, uint32_t k1, uint32_t& x0, uint32_t& x1) {
    uint32_t k2 = k0 ^ k1 ^ 0x1BD11BDAu;
    x0 += k0; x1 += k1;
    TF_ROUND_H(x0,x1,13); TF_ROUND_H(x0,x1,15); TF_ROUND_H(x0,x1,26); TF_ROUND_H(x0,x1,6);
    x0 += k1; x1 += k2 + 1u;
    TF_ROUND_H(x0,x1,17); TF_ROUND_H(x0,x1,29); TF_ROUND_H(x0,x1,16); TF_ROUND_H(x0,x1,24);
    x0 += k2; x1 += k0 + 2u;
    TF_ROUND_H(x0,x1,13); TF_ROUND_H(x0,x1,15); TF_ROUND_H(x0,x1,26); TF_ROUND_H(x0,x1,6);
    x0 += k0; x1 += k1 + 3u;
    TF_ROUND_H(x0,x1,17); TF_ROUND_H(x0,x1,29); TF_ROUND_H(x0,x1,16); TF_ROUND_H(x0,x1,24);
    x0 += k1; x1 += k2 + 4u;
    TF_ROUND_H(x0,x1,13); TF_ROUND_H(x0,x1,15); TF_ROUND_H(x0,x1,26); TF_ROUND_H(x0,x1,6);
    x0 += k2; x1 += k0 + 5u;
}

// Device: force add onto the fma pipe. `one` is a runtime kernel arg (==1);
// ptxas cannot fold mad.lo with an unknown multiplier back to IADD3.
__device__ __forceinline__ uint32_t imadd(uint32_t a, uint32_t one, uint32_t b) {
    uint32_t r;
    asm("mad.lo.u32 %0, %1, %2, %3;" : "=r"(r) : "r"(a), "r"(one), "r"(b));
    return r;
}

#define TF_ROUND_D(x0, x1, r) do { (x0) = imadd((x0), one, (x1)); (x1) = rotl32((x1), (r)) ^ (x0); } while (0)
#define TF_R4A_D(x0, x1) do { TF_ROUND_D(x0,x1,13); TF_ROUND_D(x0,x1,15); TF_ROUND_D(x0,x1,26); TF_ROUND_D(x0,x1,6);  } while (0)
#define TF_R4B_D(x0, x1) do { TF_ROUND_D(x0,x1,17); TF_ROUND_D(x0,x1,29); TF_ROUND_D(x0,x1,16); TF_ROUND_D(x0,x1,24); } while (0)

// Partitionable random_bits at counter (0, c): bits = o0 ^ o1.
__device__ __forceinline__ uint32_t pbits_f(const StreamK& s, uint32_t c, uint32_t one) {
    uint32_t x0 = s.i0;
    uint32_t x1 = imadd(c, one, s.i1);
    TF_R4A_D(x0, x1); x0 = imadd(x0, one, s.a1); x1 = imadd(x1, one, s.b1);
    TF_R4B_D(x0, x1); x0 = imadd(x0, one, s.a2); x1 = imadd(x1, one, s.b2);
    TF_R4A_D(x0, x1); x0 = imadd(x0, one, s.a3); x1 = imadd(x1, one, s.b3);
    TF_R4B_D(x0, x1); x0 = imadd(x0, one, s.a4); x1 = imadd(x1, one, s.b4);
    TF_R4A_D(x0, x1); x0 = imadd(x0, one, s.a5); x1 = imadd(x1, one, s.b5);
    return x0 ^ x1;
}

// ---------------------------------------------------------------------------
// Fused kernel: one warp per (row, channel); ch is block-uniform.
//   gen: threefry streams; uniform compare done as  bits < (thr<<9)  (exact,
//        since (bits>>9) < thr  <=>  bits < thr*512, thr <= 2^23).
//        Rare dat/sym blocks ballot-skipped.
//   scan: warp stream-compaction + insertion emit, sequential-exact.
// ---------------------------------------------------------------------------
__global__ void __launch_bounds__(256) fused_kernel(GenParams P,
                                                    const float* __restrict__ x,
                                                    const float* __restrict__ p_sub,
                                                    const float* __restrict__ p_del,
                                                    const float* __restrict__ p_ins,
                                                    float* __restrict__ out,
                                                    uint32_t one) {
    __shared__ uint8_t rowbuf[8][LCOLS];

    const uint32_t wib  = threadIdx.x >> 5;
    const uint32_t lane = threadIdx.x & 31u;
    const uint32_t ch   = blockIdx.x & 3u;                 // block-uniform
    const uint32_t b    = (blockIdx.x >> 2) * 8u + wib;    // 0..16383

    const uint32_t thr_sub9 = (uint32_t)ceilf(*p_sub * 8388608.0f) << 9;
    const uint32_t thr_del9 = (uint32_t)ceilf(*p_del * 8388608.0f) << 9;
    const uint32_t thr_ins9 = (uint32_t)ceilf(*p_ins * 8388608.0f) << 9;

    const StreamK sd = P.s[ch][0];   // data (randint)
    const StreamK sm = P.s[ch][1];   // sub mask (uniform)
    const StreamK sk = P.s[ch][2];   // del keep (uniform)
    const StreamK si = P.s[ch][3];   // ins flag (uniform)
    const StreamK ss = P.s[ch][4];   // ins sym (randint)

    const float* xrow = x + (size_t)b * LCOLS;
    float*       orow = out + ((size_t)b * 4u + ch) * LP;
    uint8_t*     srow = rowbuf[wib];

    const uint32_t lt = (1u << lane) - 1u;
    uint32_t srank = 0;   // survivors emitted so far
    uint32_t itot  = 0;   // insertions emitted so far

    #pragma unroll 1
    for (int w = 0; w < LCOLS / 32; ++w) {
        const uint32_t l  = (uint32_t)w * 32u + lane;
        const uint32_t i1 = b * LCOLS + l;   // (B,512) stream index
        const uint32_t i2 = b * LP + l;      // (B,514) stream index

        // ---- gen phase ----
        uint32_t mskb = pbits_f(sm, i1, one) < thr_sub9;
        uint32_t keep = pbits_f(sk, i1, one) >= thr_del9;
        uint32_t insf = pbits_f(si, i2, one) < thr_ins9;

        uint32_t dat = 0, sym = 0;
        if (__ballot_sync(0xffffffffu, mskb))
            dat = pbits_f(sd, i1, one) & 3u;
        if (__ballot_sync(0xffffffffu, insf))
            sym = pbits_f(ss, i2, one) & 3u;

        srow[l] = (uint8_t)(insf | (sym << 1));
        __syncwarp();

        // ---- scan phase ----
        int xi  = (int)xrow[l];
        int val = (int)(((uint32_t)xi + dat * mskb) & 3u);

        unsigned kmask = __ballot_sync(0xffffffffu, keep);
        int rank_local = __popc(kmask & lt);

        int insf2 = 0, sym2 = 0;
        if (keep) {
            // survivor rank indexes ins/sym (byte already written this chunk
            // or earlier, since rank <= current position)
            uint8_t ib = srow[srank + (uint32_t)rank_local];
            insf2 = ib & 1;
            sym2  = (ib >> 1) & 3;
        }
        unsigned imask = __ballot_sync(0xffffffffu, keep && insf2);

        if (keep) {
            uint32_t pos = srank + itot + (uint32_t)rank_local
                         + (uint32_t)__popc(imask & lt);
            if (pos < LP)                orow[pos]     = (float)(val + 1);
            if (insf2 && pos + 1 < LP)   orow[pos + 1] = (float)(sym2 + 1);
        }
        srank += __popc(kmask);
        itot  += __popc(imask);
    }

    // tail = -1 padding, +1.0 => 0.0
    uint32_t cend = srank + itot;
    if (cend > LP) cend = LP;
    for (uint32_t j = cend + lane; j < LP; j += 32) orow[j] = 0.0f;
}

// ---------------------------------------------------------------------------
// Host: derive the full JAX key tree (partitionable / fold-like semantics:
// every derived key = threefry(parent, (0, index)) giving the (o0, o1) pair),
// then prefold each leaf key's injection schedule into StreamK.
// ---------------------------------------------------------------------------
static inline void h_key(uint32_t k0, uint32_t k1, uint32_t idx,
                         uint32_t& o0, uint32_t& o1) {
    uint32_t x0 = 0u, x1 = idx;
    h_tf2(k0, k1, x0, x1);
    o0 = x0; o1 = x1;
}

static inline StreamK make_stream(uint32_t k0, uint32_t k1) {
    uint32_t k2 = k0 ^ k1 ^ 0x1BD11BDAu;
    StreamK s;
    s.i0 = k0;        s.i1 = k1;
    s.a1 = k1;        s.b1 = k2 + 1u;
    s.a2 = k2;        s.b2 = k0 + 2u;
    s.a3 = k0;        s.b3 = k1 + 3u;
    s.a4 = k1;        s.b4 = k2 + 4u;
    s.a5 = k2;        s.b5 = k0 + 5u;
    return s;
}

extern "C" void kernel_launch(void* const* d_in, const int* in_sizes, int n_in,
                              void* d_out, int out_size) {
    const float* x     = (const float*)d_in[0];
    const float* p_sub = (const float*)d_in[1];
    const float* p_del = (const float*)d_in[2];
    const float* p_ins = (const float*)d_in[3];

    GenParams P;
    const uint32_t base0 = 0u, base1 = 42u;           // jax.random.key(42) -> (0, 42)
    for (uint32_t c = 0; c < 4; ++c) {
        uint32_t kc0, kc1;
        h_key(base0, base1, c, kc0, kc1);             // fold_in(key, c)

        // split(kc, 3) fold-like: key_i = tf(kc, (0, i))
        uint32_t k1_0, k1_1, k2_0, k2_1, k3_0, k3_1;
        h_key(kc0, kc1, 0u, k1_0, k1_1);              // sub key
        h_key(kc0, kc1, 1u, k2_0, k2_1);              // del key
        h_key(kc0, kc1, 2u, k3_0, k3_1);              // ins key

        // sub: split(k1, 2) -> data key (randint, internal split child 1),
        //                      mask key (uniform)
        uint32_t kd0, kd1, kdl0, kdl1, km0, km1;
        h_key(k1_0, k1_1, 0u, kd0, kd1);
        h_key(kd0, kd1, 1u, kdl0, kdl1);              // _randint lower_bits key
        h_key(k1_0, k1_1, 1u, km0, km1);

        // ins: split(k3, 2) -> flag key (uniform), sym key (randint child 1)
        uint32_t kf0, kf1, ks0, ks1, ksl0, ksl1;
        h_key(k3_0, k3_1, 0u, kf0, kf1);
        h_key(k3_0, k3_1, 1u, ks0, ks1);
        h_key(ks0, ks1, 1u, ksl0, ksl1);

        P.s[c][0] = make_stream(kdl0, kdl1);          // data
        P.s[c][1] = make_stream(km0, km1);            // sub mask
        P.s[c][2] = make_stream(k2_0, k2_1);          // del keep
        P.s[c][3] = make_stream(kf0, kf1);            // ins flag
        P.s[c][4] = make_stream(ksl0, ksl1);          // ins sym
    }

    // 65536 warps (one per row x channel) = 8192 blocks x 256 threads
    fused_kernel<<<8192, 256>>>(P, x, p_sub, p_del, p_ins, (float*)d_out, 1u);
}